// round 1
// baseline (speedup 1.0000x reference)
#include <cuda_runtime.h>
#include <math.h>

// Problem constants (fixed by dataset)
#define NN 20000
#define EE 100000
#define CC 32
#define NHEAD 4
#define DH 8
#define NB 16
#define HID 64

// Scratch (static __device__ — no allocation allowed)
__device__ float g_q[NN * CC];       // query, scaled by 1/sqrt(C)
__device__ float g_Pbk[NN * CC];     // b2-term for K path, scaled by tp_norm
__device__ float g_Pbv[NN * CC];     // b2-term for V path
__device__ float g_Pk[(size_t)NN * 2048];  // P[n, h*32+k] for K MLP, scaled by tp_norm
__device__ float g_Pv[(size_t)NN * 2048];  // P for V MLP
__device__ float g_den[NN * NHEAD];  // softmax denominators
__device__ float g_num[NN * CC];     // softmax-weighted V accumulation

__device__ __forceinline__ float decode_scalar(const int* p) {
    // max_radius might arrive as int32 or float32 bits; disambiguate.
    int iv = *p;
    if (iv > -(1 << 23) && iv < (1 << 23)) return (float)iv;
    return __int_as_float(iv);
}

#define INV_SQRT_C 0.17677669529663687f      /* 1/sqrt(32) */
#define DOT_SCALE  0.04419417382415922f      /* (1/8) * (1/sqrt(8)) */

// ---------------------------------------------------------------------------
// K0: zero the accumulators (must run every graph replay)
// ---------------------------------------------------------------------------
__global__ void k0_init(int n) {
    int i = blockIdx.x * blockDim.x + threadIdx.x;
    int nc = n * CC;
    if (i < nc) g_num[i] = 0.f;
    else if (i < nc + n * NHEAD) g_den[i - nc] = 0.f;
}

// ---------------------------------------------------------------------------
// K1: per-node small projections: q = nf@w_q/sqrt(C), and the b2 bias terms
//     Pb*[n,k] = tp_norm * sum_i nf[n,i]*b2[i*32+k]
// One warp per node; lane = output channel.
// ---------------------------------------------------------------------------
__global__ void k1_node_pre(const float* __restrict__ nf,
                            const float* __restrict__ w_q,
                            const float* __restrict__ b2k,
                            const float* __restrict__ b2v, int n) {
    __shared__ float s_wq[1024], s_bk[1024], s_bv[1024];
    for (int i = threadIdx.x; i < 1024; i += blockDim.x) {
        s_wq[i] = w_q[i];
        s_bk[i] = b2k[i];
        s_bv[i] = b2v[i];
    }
    __syncthreads();
    int warp = threadIdx.x >> 5;
    int lane = threadIdx.x & 31;
    int node = blockIdx.x * (blockDim.x >> 5) + warp;
    if (node >= n) return;
    float fv = nf[node * 32 + lane];
    float q = 0.f, bk = 0.f, bv = 0.f;
#pragma unroll
    for (int i = 0; i < 32; i++) {
        float a = __shfl_sync(0xffffffffu, fv, i);
        q  += a * s_wq[i * 32 + lane];
        bk += a * s_bk[i * 32 + lane];
        bv += a * s_bv[i * 32 + lane];
    }
    g_q[node * 32 + lane]   = q  * INV_SQRT_C;
    g_Pbk[node * 32 + lane] = bk * INV_SQRT_C;
    g_Pbv[node * 32 + lane] = bv * INV_SQRT_C;
}

// ---------------------------------------------------------------------------
// K2: P precompute GEMM.  P[n, h*32+k] = tp_norm * sum_i nf[n,i] * w2[h, i*32+k]
// Viewed as (n x 32) @ (32 x 2048) with B[i, h*32+k] = w2[h*1024 + i*32 + k].
// Tiles: 128 nodes x 128 outputs (= 4 hidden units), K=32 in one shot.
// 256 threads, 8x8 register tile each.
// grid.z selects K-MLP vs V-MLP.
// ---------------------------------------------------------------------------
__global__ void __launch_bounds__(256) k2_pgemm(const float* __restrict__ nf,
                                                const float* __restrict__ w2k,
                                                const float* __restrict__ w2v,
                                                int n) {
    __shared__ float As[32][128];   // As[k][node]
    __shared__ float Bs[32][128];   // Bs[i][j]  (j = hh*32 + k_out)
    const float* W = blockIdx.z ? w2v : w2k;
    float* P = blockIdx.z ? g_Pv : g_Pk;
    int n0 = blockIdx.x * 128;
    int h0 = blockIdx.y * 4;        // 4 hidden units per 128-wide output tile
    int tid = threadIdx.x;

    // Load A tile (transposed into smem)
#pragma unroll
    for (int p = 0; p < 4; p++) {
        int f4 = p * 256 + tid;       // float4 index, 1024 total
        int node = f4 >> 3;
        int k4 = (f4 & 7) << 2;
        float4 v = make_float4(0.f, 0.f, 0.f, 0.f);
        if (n0 + node < n) v = *(const float4*)(nf + (size_t)(n0 + node) * 32 + k4);
        As[k4 + 0][node] = v.x;
        As[k4 + 1][node] = v.y;
        As[k4 + 2][node] = v.z;
        As[k4 + 3][node] = v.w;
    }
    // Load B tile: 4 contiguous 1024-float rows of w2 starting at h0
    const float* Wb = W + h0 * 1024;
#pragma unroll
    for (int p = 0; p < 4; p++) {
        int f4 = p * 256 + tid;                // 1024 float4 = 4096 floats
        float4 v = *(const float4*)(Wb + f4 * 4);
        int idx = f4 * 4;
        int hh  = idx >> 10;
        int rem = idx & 1023;
        int i   = rem >> 5;
        int k   = rem & 31;
        *(float4*)(&Bs[i][hh * 32 + k]) = v;
    }
    __syncthreads();

    int tr = tid >> 4, tc = tid & 15;
    float acc[8][8];
#pragma unroll
    for (int r = 0; r < 8; r++)
#pragma unroll
        for (int c = 0; c < 8; c++) acc[r][c] = 0.f;

#pragma unroll
    for (int k = 0; k < 32; k++) {
        float a[8], b[8];
        *(float4*)(a)     = *(float4*)(&As[k][tr * 8]);
        *(float4*)(a + 4) = *(float4*)(&As[k][tr * 8 + 4]);
        *(float4*)(b)     = *(float4*)(&Bs[k][tc * 8]);
        *(float4*)(b + 4) = *(float4*)(&Bs[k][tc * 8 + 4]);
#pragma unroll
        for (int r = 0; r < 8; r++)
#pragma unroll
            for (int c = 0; c < 8; c++) acc[r][c] += a[r] * b[c];
    }

    int j0 = blockIdx.y * 128 + tc * 8;
#pragma unroll
    for (int r = 0; r < 8; r++) {
        int node = n0 + tr * 8 + r;
        if (node < n) {
            float* dst = P + (size_t)node * 2048 + j0;
            float4 o;
            o.x = acc[r][0] * INV_SQRT_C; o.y = acc[r][1] * INV_SQRT_C;
            o.z = acc[r][2] * INV_SQRT_C; o.w = acc[r][3] * INV_SQRT_C;
            *(float4*)(dst) = o;
            o.x = acc[r][4] * INV_SQRT_C; o.y = acc[r][5] * INV_SQRT_C;
            o.z = acc[r][6] * INV_SQRT_C; o.w = acc[r][7] * INV_SQRT_C;
            *(float4*)(dst + 4) = o;
        }
    }
}

// ---------------------------------------------------------------------------
// K3: fused edge pass. One warp per edge; lane = channel.
//   - radial MLP layer 1 (+ SiLU) for K and V -> hidden[64] each
//   - k/v edge = sh * (sum_h hidden_h * P[src,h,lane] + Pb[src,lane])
//   - per-head bilinear logits with w_dot, cutoff, exp
//   - atomicAdd into den / num (softmax without max-shift: logits are O(0.5))
// ---------------------------------------------------------------------------
__global__ void __launch_bounds__(256) k3_edge(
    const int* __restrict__ ei, const float* __restrict__ esh,
    const float* __restrict__ remb, const float* __restrict__ elen,
    const float* __restrict__ w1k, const float* __restrict__ b1k,
    const float* __restrict__ w1v, const float* __restrict__ b1v,
    const float* __restrict__ wdot, const int* __restrict__ maxr_p,
    int e_count) {
    __shared__ float s_w1k[NB * HID], s_w1v[NB * HID];
    __shared__ float s_b1k[HID], s_b1v[HID];
    __shared__ float s_wdot[DH * DH];
    for (int i = threadIdx.x; i < NB * HID; i += blockDim.x) {
        s_w1k[i] = w1k[i];
        s_w1v[i] = w1v[i];
    }
    if (threadIdx.x < HID) {
        s_b1k[threadIdx.x] = b1k[threadIdx.x];
        s_b1v[threadIdx.x] = b1v[threadIdx.x];
    }
    if (threadIdx.x < DH * DH) s_wdot[threadIdx.x] = wdot[threadIdx.x];
    __syncthreads();

    int warp = threadIdx.x >> 5;
    int lane = threadIdx.x & 31;
    int e = blockIdx.x * (blockDim.x >> 5) + warp;
    if (e >= e_count) return;

    int src = ei[e];
    int dst = ei[e_count + e];
    float shv = esh[e];

    // radial MLP hidden layer (lane owns hidden units lane and lane+32)
    float rv = (lane < NB) ? remb[e * NB + lane] : 0.f;
    float zk0 = s_b1k[lane], zk1 = s_b1k[lane + 32];
    float zv0 = s_b1v[lane], zv1 = s_b1v[lane + 32];
#pragma unroll
    for (int r = 0; r < NB; r++) {
        float x = __shfl_sync(0xffffffffu, rv, r);
        zk0 += x * s_w1k[r * HID + lane];
        zk1 += x * s_w1k[r * HID + lane + 32];
        zv0 += x * s_w1v[r * HID + lane];
        zv1 += x * s_w1v[r * HID + lane + 32];
    }
    float hk0 = zk0 / (1.f + expf(-zk0));
    float hk1 = zk1 / (1.f + expf(-zk1));
    float hv0 = zv0 / (1.f + expf(-zv0));
    float hv1 = zv1 / (1.f + expf(-zv1));

    // contract hidden with per-node precomputed P rows
    const float* Pk = g_Pk + (size_t)src * 2048;
    const float* Pv = g_Pv + (size_t)src * 2048;
    float ak = g_Pbk[src * 32 + lane];
    float av = g_Pbv[src * 32 + lane];
#pragma unroll
    for (int h = 0; h < HID; h++) {
        float bk = __shfl_sync(0xffffffffu, (h < 32) ? hk0 : hk1, h & 31);
        float bv = __shfl_sync(0xffffffffu, (h < 32) ? hv0 : hv1, h & 31);
        ak += bk * Pk[h * 32 + lane];
        av += bv * Pv[h * 32 + lane];
    }
    float k_e = shv * ak;   // tp_norm already folded into P/Pb
    float v_e = shv * av;

    // per-head bilinear logit: sum_{i,j} q_i k_j wdot[i][j]
    int head = lane >> 3;
    int j = lane & 7;
    float qv = g_q[dst * 32 + lane];   // already /sqrt(C)
    float cj = 0.f;
#pragma unroll
    for (int i = 0; i < DH; i++) {
        float qi = __shfl_sync(0xffffffffu, qv, head * 8 + i);
        cj += qi * s_wdot[i * 8 + j];
    }
    float prod = cj * k_e;
    prod += __shfl_xor_sync(0xffffffffu, prod, 1);
    prod += __shfl_xor_sync(0xffffffffu, prod, 2);
    prod += __shfl_xor_sync(0xffffffffu, prod, 4);

    float max_r = decode_scalar(maxr_p);
    float L = elen[e];
    float cut = 1.f / (1.f + expf(-10.f * (1.f - L / max_r)));
    float logit = prod * DOT_SCALE * cut;
    float ex = expf(logit);     // |logit| << 1 by construction; no max-shift needed

    if (j == 0) atomicAdd(&g_den[dst * NHEAD + head], ex);
    atomicAdd(&g_num[dst * 32 + lane], ex * v_e);
}

// ---------------------------------------------------------------------------
// K5: per-node epilogue: agg = num/den, out-proj + skip, FFN, final skip.
// One warp per node; lane = channel.
// ---------------------------------------------------------------------------
__global__ void k5_final(const float* __restrict__ nf,
                         const float* __restrict__ w_out,
                         const float* __restrict__ ffn_w1,
                         const float* __restrict__ ffn_w2,
                         float* __restrict__ out, int n) {
    __shared__ float s_wo[1024], s_f1[2048], s_f2[2048];
    for (int i = threadIdx.x; i < 1024; i += blockDim.x) s_wo[i] = w_out[i];
    for (int i = threadIdx.x; i < 2048; i += blockDim.x) {
        s_f1[i] = ffn_w1[i];
        s_f2[i] = ffn_w2[i];
    }
    __syncthreads();
    int warp = threadIdx.x >> 5;
    int lane = threadIdx.x & 31;
    int node = blockIdx.x * (blockDim.x >> 5) + warp;
    if (node >= n) return;

    float numv = g_num[node * 32 + lane];
    float den = g_den[node * NHEAD + (lane >> 3)];
    float agg = (den > 0.f) ? numv / den : 0.f;   // isolated nodes: agg = 0 (matches ref)

    float o = 0.f;
#pragma unroll
    for (int i = 0; i < 32; i++) {
        float a = __shfl_sync(0xffffffffu, agg, i);
        o += a * s_wo[i * 32 + lane];
    }
    float attn = nf[node * 32 + lane] + o * INV_SQRT_C;

    float h0 = 0.f, h1 = 0.f;
#pragma unroll
    for (int i = 0; i < 32; i++) {
        float a = __shfl_sync(0xffffffffu, attn, i);
        h0 += a * s_f1[i * 64 + lane];
        h1 += a * s_f1[i * 64 + lane + 32];
    }
    h0 *= INV_SQRT_C;
    h1 *= INV_SQRT_C;
    // NormActivation for scalars: x * sigmoid(|x|)
    float g0 = h0 / (1.f + expf(-fabsf(h0)));
    float g1 = h1 / (1.f + expf(-fabsf(h1)));

    float f = 0.f;
#pragma unroll
    for (int jj = 0; jj < 64; jj++) {
        float g = __shfl_sync(0xffffffffu, (jj < 32) ? g0 : g1, jj & 31);
        f += g * s_f2[jj * 32 + lane];
    }
    out[node * 32 + lane] = attn + f * 0.125f;   // 1/sqrt(2C) = 1/8
}

// ---------------------------------------------------------------------------
extern "C" void kernel_launch(void* const* d_in, const int* in_sizes, int n_in,
                              void* d_out, int out_size) {
    const float* nf     = (const float*)d_in[0];
    const int*   ei     = (const int*)d_in[1];
    const float* esh    = (const float*)d_in[2];
    const float* remb   = (const float*)d_in[3];
    const float* elen   = (const float*)d_in[4];
    const int*   maxr   = (const int*)d_in[5];
    const float* w_q    = (const float*)d_in[6];
    const float* fck_w1 = (const float*)d_in[7];
    const float* fck_b1 = (const float*)d_in[8];
    const float* fck_w2 = (const float*)d_in[9];
    const float* fck_b2 = (const float*)d_in[10];
    const float* fcv_w1 = (const float*)d_in[11];
    const float* fcv_b1 = (const float*)d_in[12];
    const float* fcv_w2 = (const float*)d_in[13];
    const float* fcv_b2 = (const float*)d_in[14];
    const float* w_dot  = (const float*)d_in[15];
    const float* w_out  = (const float*)d_in[16];
    const float* ffn_w1 = (const float*)d_in[17];
    const float* ffn_w2 = (const float*)d_in[18];

    int n = in_sizes[0] / CC;
    int e = in_sizes[1] / 2;

    int tot = n * (CC + NHEAD);
    k0_init<<<(tot + 255) / 256, 256>>>(n);
    k1_node_pre<<<(n + 7) / 8, 256>>>(nf, w_q, fck_b2, fcv_b2, n);
    dim3 g2((n + 127) / 128, 16, 2);
    k2_pgemm<<<g2, 256>>>(nf, fck_w2, fcv_w2, n);
    k3_edge<<<(e + 7) / 8, 256>>>(ei, esh, remb, elen, fck_w1, fck_b1,
                                  fcv_w1, fcv_b1, w_dot, maxr, e);
    k5_final<<<(n + 7) / 8, 256>>>(nf, w_out, ffn_w1, ffn_w2, (float*)d_out, n);
}